// round 1
// baseline (speedup 1.0000x reference)
#include <cuda_runtime.h>
#include <cstdint>

#define BATCH 32
#define CHANNELS 3
#define HIMG 512
#define WIMG 512
#define NPIX (BATCH * HIMG * WIMG)          // 8388608
#define NELEM ((double)(BATCH * CHANNELS * HIMG * WIMG))

// Scratch (no cudaMalloc allowed): inverted homographies (pred 0..31, true 32..63)
__device__ float  g_Hinv[2 * BATCH * 9];
__device__ double g_acc;

// ---------------------------------------------------------------------------
// Kernel 0: zero accumulator + invert 3x3 homographies via adjugate
// ---------------------------------------------------------------------------
__global__ void pl_init_kernel(const float* __restrict__ Hp,
                               const float* __restrict__ Ht) {
    int t = threadIdx.x;
    if (t == 0) g_acc = 0.0;
    if (t < 2 * BATCH) {
        const float* src = (t < BATCH) ? (Hp + t * 9) : (Ht + (t - BATCH) * 9);
        float m[9];
#pragma unroll
        for (int i = 0; i < 9; i++) m[i] = src[i];
        float c00 = m[4] * m[8] - m[5] * m[7];
        float c01 = m[5] * m[6] - m[3] * m[8];
        float c02 = m[3] * m[7] - m[4] * m[6];
        float det = m[0] * c00 + m[1] * c01 + m[2] * c02;
        float id  = 1.0f / det;
        float inv[9];
        inv[0] = c00 * id;
        inv[1] = (m[2] * m[7] - m[1] * m[8]) * id;
        inv[2] = (m[1] * m[5] - m[2] * m[4]) * id;
        inv[3] = c01 * id;
        inv[4] = (m[0] * m[8] - m[2] * m[6]) * id;
        inv[5] = (m[2] * m[3] - m[0] * m[5]) * id;
        inv[6] = c02 * id;
        inv[7] = (m[1] * m[6] - m[0] * m[7]) * id;
        inv[8] = (m[0] * m[4] - m[1] * m[3]) * id;
#pragma unroll
        for (int i = 0; i < 9; i++) g_Hinv[t * 9 + i] = inv[i];
    }
}

// ---------------------------------------------------------------------------
// Bilinear tap setup: given sample coords (sx,sy) produce 4 clamped linear
// offsets, 4 weights (weight==0 if tap invalid -> zero padding semantics)
// ---------------------------------------------------------------------------
struct Taps {
    int   o00, o10, o01, o11;   // offsets within a channel plane
    float w00, w10, w01, w11;   // weights (0 for out-of-bounds taps)
};

__device__ __forceinline__ Taps make_taps(float sx, float sy) {
    Taps tp;
    float x0f = floorf(sx), y0f = floorf(sy);
    float wx1 = sx - x0f, wx0 = 1.0f - wx1;
    float wy1 = sy - y0f, wy0 = 1.0f - wy1;
    int x0 = (int)x0f, y0 = (int)y0f;
    int x1 = x0 + 1,   y1 = y0 + 1;
    bool vx0 = (x0 >= 0) & (x0 < WIMG);
    bool vx1 = (x1 >= 0) & (x1 < WIMG);
    bool vy0 = (y0 >= 0) & (y0 < HIMG);
    bool vy1 = (y1 >= 0) & (y1 < HIMG);
    int cx0 = min(max(x0, 0), WIMG - 1);
    int cx1 = min(max(x1, 0), WIMG - 1);
    int cy0 = min(max(y0, 0), HIMG - 1);
    int cy1 = min(max(y1, 0), HIMG - 1);
    tp.o00 = cy0 * WIMG + cx0;
    tp.o10 = cy0 * WIMG + cx1;
    tp.o01 = cy1 * WIMG + cx0;
    tp.o11 = cy1 * WIMG + cx1;
    tp.w00 = (vx0 & vy0) ? wx0 * wy0 : 0.0f;
    tp.w10 = (vx1 & vy0) ? wx1 * wy0 : 0.0f;
    tp.w01 = (vx0 & vy1) ? wx0 * wy1 : 0.0f;
    tp.w11 = (vx1 & vy1) ? wx1 * wy1 : 0.0f;
    return tp;
}

__device__ __forceinline__ float sample(const float* __restrict__ img, const Taps& t) {
    float v = __ldg(img + t.o00) * t.w00;
    v = fmaf(__ldg(img + t.o10), t.w10, v);
    v = fmaf(__ldg(img + t.o01), t.w01, v);
    v = fmaf(__ldg(img + t.o11), t.w11, v);
    return v;
}

// Homography -> sample coords replicating the reference's exact formulas
__device__ __forceinline__ void warp_coords(const float* __restrict__ h,
                                            float fx, float fy,
                                            float& sx, float& sy) {
    float X = fmaf(h[0], fx, fmaf(h[1], fy, h[2]));
    float Y = fmaf(h[3], fx, fmaf(h[4], fy, h[5]));
    float Z = fmaf(h[6], fx, fmaf(h[7], fy, h[8]));
    float iz = 1.0f / Z;
    float nx = X * iz;
    float ny = Y * iz;
    // x_norm = 2*nx/(W-1) - 1 ; sx = ((x_norm+1)*W - 1)*0.5
    float xn = 2.0f * nx * (1.0f / (WIMG - 1)) - 1.0f;
    float yn = 2.0f * ny * (1.0f / (HIMG - 1)) - 1.0f;
    sx = ((xn + 1.0f) * WIMG - 1.0f) * 0.5f;
    sy = ((yn + 1.0f) * HIMG - 1.0f) * 0.5f;
}

// ---------------------------------------------------------------------------
// Kernel 1: main — one thread per (b,y,x) pixel
// ---------------------------------------------------------------------------
__global__ void __launch_bounds__(256)
pl_main_kernel(const float* __restrict__ I) {
    int idx = blockIdx.x * blockDim.x + threadIdx.x;  // < NPIX (exact power of 2)
    int x = idx & (WIMG - 1);
    int y = (idx >> 9) & (HIMG - 1);
    int b = idx >> 18;

    // load both inverse homographies (broadcast within warp via L1)
    float hp[9], ht[9];
#pragma unroll
    for (int i = 0; i < 9; i++) hp[i] = g_Hinv[b * 9 + i];
#pragma unroll
    for (int i = 0; i < 9; i++) ht[i] = g_Hinv[(BATCH + b) * 9 + i];

    float fx = (float)x, fy = (float)y;
    float pxs, pys, txs, tys;
    warp_coords(hp, fx, fy, pxs, pys);
    warp_coords(ht, fx, fy, txs, tys);

    Taps tpP = make_taps(pxs, pys);
    Taps tpT = make_taps(txs, tys);

    const float* imgB = I + (size_t)b * CHANNELS * HIMG * WIMG;
    float acc = 0.0f;
#pragma unroll
    for (int c = 0; c < CHANNELS; c++) {
        const float* img = imgB + c * (HIMG * WIMG);
        float p = sample(img, tpP);
        float t = sample(img, tpT);
        float d = p - t;
        acc = fmaf(d, d, acc);
    }

    // reduce: warp shuffle -> shared -> one atomicAdd(double) per block
#pragma unroll
    for (int off = 16; off > 0; off >>= 1)
        acc += __shfl_down_sync(0xFFFFFFFFu, acc, off);

    __shared__ float s_part[8];  // 256 threads = 8 warps
    int lane = threadIdx.x & 31, wid = threadIdx.x >> 5;
    if (lane == 0) s_part[wid] = acc;
    __syncthreads();
    if (wid == 0) {
        float v = (lane < 8) ? s_part[lane] : 0.0f;
#pragma unroll
        for (int off = 4; off > 0; off >>= 1)
            v += __shfl_down_sync(0xFFFFFFFFu, v, off);
        if (lane == 0) atomicAdd(&g_acc, (double)v);
    }
}

// ---------------------------------------------------------------------------
// Kernel 2: finalize
// ---------------------------------------------------------------------------
__global__ void pl_final_kernel(float* __restrict__ out) {
    out[0] = (float)(g_acc / NELEM);
}

extern "C" void kernel_launch(void* const* d_in, const int* in_sizes, int n_in,
                              void* d_out, int out_size) {
    const float* Hp = (const float*)d_in[0];
    const float* Ht = (const float*)d_in[1];
    const float* I  = (const float*)d_in[2];
    float* out = (float*)d_out;

    pl_init_kernel<<<1, 64>>>(Hp, Ht);
    pl_main_kernel<<<NPIX / 256, 256>>>(I);
    pl_final_kernel<<<1, 1>>>(out);
}

// round 2
// speedup vs baseline: 1.1238x; 1.1238x over previous
#include <cuda_runtime.h>

#define BATCH     32
#define CHANNELS  3
#define HIMG      512
#define WIMG      512
#define PLANE     (HIMG * WIMG)
#define THREADS   256
// one block per (batch, row): 32*512 = 16384 blocks; each thread does 2 x-pixels
#define NBLOCKS   (BATCH * HIMG)
#define INV_NELEM (1.0f / (float)(BATCH * CHANNELS * HIMG * WIMG))

// ---------------------------------------------------------------------------
// 3x3 inverse via adjugate (near-identity input -> well-conditioned)
// ---------------------------------------------------------------------------
__device__ __forceinline__ void invert3x3(const float* __restrict__ m,
                                          float* __restrict__ inv) {
    float c00 = m[4] * m[8] - m[5] * m[7];
    float c01 = m[5] * m[6] - m[3] * m[8];
    float c02 = m[3] * m[7] - m[4] * m[6];
    float det = m[0] * c00 + m[1] * c01 + m[2] * c02;
    float id  = 1.0f / det;
    inv[0] = c00 * id;
    inv[1] = (m[2] * m[7] - m[1] * m[8]) * id;
    inv[2] = (m[1] * m[5] - m[2] * m[4]) * id;
    inv[3] = c01 * id;
    inv[4] = (m[0] * m[8] - m[2] * m[6]) * id;
    inv[5] = (m[2] * m[3] - m[0] * m[5]) * id;
    inv[6] = c02 * id;
    inv[7] = (m[1] * m[6] - m[0] * m[7]) * id;
    inv[8] = (m[0] * m[4] - m[1] * m[3]) * id;
}

// ---------------------------------------------------------------------------
// Bilinear taps with zero-padding semantics (weight = 0 when tap OOB)
// ---------------------------------------------------------------------------
struct Taps {
    int   o00, o10, o01, o11;
    float w00, w10, w01, w11;
};

__device__ __forceinline__ Taps make_taps(float sx, float sy) {
    Taps tp;
    float x0f = floorf(sx), y0f = floorf(sy);
    float wx1 = sx - x0f, wx0 = 1.0f - wx1;
    float wy1 = sy - y0f, wy0 = 1.0f - wy1;
    int x0 = (int)x0f, y0 = (int)y0f;
    int x1 = x0 + 1,   y1 = y0 + 1;
    bool vx0 = (x0 >= 0) & (x0 < WIMG);
    bool vx1 = (x1 >= 0) & (x1 < WIMG);
    bool vy0 = (y0 >= 0) & (y0 < HIMG);
    bool vy1 = (y1 >= 0) & (y1 < HIMG);
    int cx0 = min(max(x0, 0), WIMG - 1);
    int cx1 = min(max(x1, 0), WIMG - 1);
    int cy0 = min(max(y0, 0), HIMG - 1);
    int cy1 = min(max(y1, 0), HIMG - 1);
    tp.o00 = cy0 * WIMG + cx0;
    tp.o10 = cy0 * WIMG + cx1;
    tp.o01 = cy1 * WIMG + cx0;
    tp.o11 = cy1 * WIMG + cx1;
    tp.w00 = (vx0 & vy0) ? wx0 * wy0 : 0.0f;
    tp.w10 = (vx1 & vy0) ? wx1 * wy0 : 0.0f;
    tp.w01 = (vx0 & vy1) ? wx0 * wy1 : 0.0f;
    tp.w11 = (vx1 & vy1) ? wx1 * wy1 : 0.0f;
    return tp;
}

__device__ __forceinline__ float sample(const float* __restrict__ img, const Taps& t) {
    float v = __ldg(img + t.o00) * t.w00;
    v = fmaf(__ldg(img + t.o10), t.w10, v);
    v = fmaf(__ldg(img + t.o01), t.w01, v);
    v = fmaf(__ldg(img + t.o11), t.w11, v);
    return v;
}

// projective coords (X,Y,Z) -> bilinear sample coords, folded constants:
// sx = (X/Z) * W/(W-1) - 0.5   (exactly equivalent to the reference chain
//  up to ~1e-7 rounding, well inside the 1e-3 gate)
#define CW (512.0f / 511.0f)
#define CH (512.0f / 511.0f)

__device__ __forceinline__ Taps proj_taps(float X, float Y, float Z) {
    float iz = __fdividef(1.0f, Z);
    float sx = fmaf(X * iz, CW, -0.5f);
    float sy = fmaf(Y * iz, CH, -0.5f);
    return make_taps(sx, sy);
}

// ---------------------------------------------------------------------------
// Fused kernel: block = one (batch,row); thread = 2 consecutive x pixels
// ---------------------------------------------------------------------------
__global__ void __launch_bounds__(THREADS)
pl_kernel(const float* __restrict__ Hp, const float* __restrict__ Ht,
          const float* __restrict__ I, float* __restrict__ out) {
    __shared__ float shp[9];
    __shared__ float sht[9];
    __shared__ float s_part[THREADS / 32];

    int tid = threadIdx.x;
    int b = blockIdx.x >> 9;         // 512 rows per batch
    int y = blockIdx.x & (HIMG - 1);

    if (tid == 0) invert3x3(Hp + b * 9, shp);
    if (tid == 1) invert3x3(Ht + b * 9, sht);
    __syncthreads();

    int x0 = tid * 2;                // this thread's two pixels: x0, x0+1
    float fx = (float)x0, fy = (float)y;

    // projective coords for pixel 0; pixel 1 = +h[col0] increments
    float Xp = fmaf(shp[0], fx, fmaf(shp[1], fy, shp[2]));
    float Yp = fmaf(shp[3], fx, fmaf(shp[4], fy, shp[5]));
    float Zp = fmaf(shp[6], fx, fmaf(shp[7], fy, shp[8]));
    float Xt = fmaf(sht[0], fx, fmaf(sht[1], fy, sht[2]));
    float Yt = fmaf(sht[3], fx, fmaf(sht[4], fy, sht[5]));
    float Zt = fmaf(sht[6], fx, fmaf(sht[7], fy, sht[8]));

    Taps tpP0 = proj_taps(Xp, Yp, Zp);
    Taps tpT0 = proj_taps(Xt, Yt, Zt);
    Taps tpP1 = proj_taps(Xp + shp[0], Yp + shp[3], Zp + shp[6]);
    Taps tpT1 = proj_taps(Xt + sht[0], Yt + sht[3], Zt + sht[6]);

    const float* imgB = I + (size_t)b * (CHANNELS * PLANE);
    float acc = 0.0f;
#pragma unroll
    for (int c = 0; c < CHANNELS; c++) {
        const float* img = imgB + c * PLANE;
        float p0 = sample(img, tpP0);
        float t0 = sample(img, tpT0);
        float p1 = sample(img, tpP1);
        float t1 = sample(img, tpT1);
        float d0 = p0 - t0;
        float d1 = p1 - t1;
        acc = fmaf(d0, d0, acc);
        acc = fmaf(d1, d1, acc);
    }

    // warp shuffle -> smem -> one float atomic per block (pre-scaled)
#pragma unroll
    for (int off = 16; off > 0; off >>= 1)
        acc += __shfl_down_sync(0xFFFFFFFFu, acc, off);

    int lane = tid & 31, wid = tid >> 5;
    if (lane == 0) s_part[wid] = acc;
    __syncthreads();
    if (wid == 0) {
        float v = (lane < THREADS / 32) ? s_part[lane] : 0.0f;
#pragma unroll
        for (int off = 4; off > 0; off >>= 1)
            v += __shfl_down_sync(0xFFFFFFFFu, v, off);
        if (lane == 0) atomicAdd(out, v * INV_NELEM);
    }
}

extern "C" void kernel_launch(void* const* d_in, const int* in_sizes, int n_in,
                              void* d_out, int out_size) {
    const float* Hp = (const float*)d_in[0];
    const float* Ht = (const float*)d_in[1];
    const float* I  = (const float*)d_in[2];
    float* out = (float*)d_out;

    cudaMemsetAsync(out, 0, sizeof(float));
    pl_kernel<<<NBLOCKS, THREADS>>>(Hp, Ht, I, out);
}

// round 3
// speedup vs baseline: 1.2550x; 1.1167x over previous
#include <cuda_runtime.h>

#define BATCH     32
#define CHANNELS  3
#define HIMG      512
#define WIMG      512
#define PLANE     (HIMG * WIMG)
#define THREADS   256
#define NBLOCKS   (BATCH * HIMG)     // one block per (batch,row)
#define INV_NELEM (1.0f / (float)(BATCH * CHANNELS * HIMG * WIMG))

// ---------------------------------------------------------------------------
// 3x3 inverse via adjugate (near-identity input -> well-conditioned)
// ---------------------------------------------------------------------------
__device__ __forceinline__ void invert3x3(const float* __restrict__ m,
                                          float* __restrict__ inv) {
    float c00 = m[4] * m[8] - m[5] * m[7];
    float c01 = m[5] * m[6] - m[3] * m[8];
    float c02 = m[3] * m[7] - m[4] * m[6];
    float det = m[0] * c00 + m[1] * c01 + m[2] * c02;
    float id  = 1.0f / det;
    inv[0] = c00 * id;
    inv[1] = (m[2] * m[7] - m[1] * m[8]) * id;
    inv[2] = (m[1] * m[5] - m[2] * m[4]) * id;
    inv[3] = c01 * id;
    inv[4] = (m[0] * m[8] - m[2] * m[6]) * id;
    inv[5] = (m[2] * m[3] - m[0] * m[5]) * id;
    inv[6] = c02 * id;
    inv[7] = (m[1] * m[6] - m[0] * m[7]) * id;
    inv[8] = (m[0] * m[4] - m[1] * m[3]) * id;
}

// ---------------------------------------------------------------------------
// Bilinear taps, zero-padding semantics (weight==0 marks an invalid tap;
// loads are predicated on weight!=0 so OOB taps cost no L1 wavefronts)
// ---------------------------------------------------------------------------
struct Taps {
    int   o00, o10, o01, o11;
    float w00, w10, w01, w11;
};

__device__ __forceinline__ Taps make_taps(float sx, float sy) {
    Taps tp;
    float x0f = floorf(sx), y0f = floorf(sy);
    float wx1 = sx - x0f, wx0 = 1.0f - wx1;
    float wy1 = sy - y0f, wy0 = 1.0f - wy1;
    int x0 = (int)x0f, y0 = (int)y0f;
    int x1 = x0 + 1,   y1 = y0 + 1;
    bool vx0 = (x0 >= 0) & (x0 < WIMG);
    bool vx1 = (x1 >= 0) & (x1 < WIMG);
    bool vy0 = (y0 >= 0) & (y0 < HIMG);
    bool vy1 = (y1 >= 0) & (y1 < HIMG);
    int cx0 = min(max(x0, 0), WIMG - 1);
    int cx1 = min(max(x1, 0), WIMG - 1);
    int cy0 = min(max(y0, 0), HIMG - 1);
    int cy1 = min(max(y1, 0), HIMG - 1);
    tp.o00 = cy0 * WIMG + cx0;
    tp.o10 = cy0 * WIMG + cx1;
    tp.o01 = cy1 * WIMG + cx0;
    tp.o11 = cy1 * WIMG + cx1;
    tp.w00 = (vx0 & vy0) ? wx0 * wy0 : 0.0f;
    tp.w10 = (vx1 & vy0) ? wx1 * wy0 : 0.0f;
    tp.w01 = (vx0 & vy1) ? wx0 * wy1 : 0.0f;
    tp.w11 = (vx1 & vy1) ? wx1 * wy1 : 0.0f;
    return tp;
}

// predicated gather: OOB taps (w==0) issue no memory access
__device__ __forceinline__ float sample(const float* __restrict__ img, const Taps& t) {
    float v = 0.0f;
    v = fmaf((t.w00 != 0.0f) ? __ldg(img + t.o00) : 0.0f, t.w00, v);
    v = fmaf((t.w10 != 0.0f) ? __ldg(img + t.o10) : 0.0f, t.w10, v);
    v = fmaf((t.w01 != 0.0f) ? __ldg(img + t.o01) : 0.0f, t.w01, v);
    v = fmaf((t.w11 != 0.0f) ? __ldg(img + t.o11) : 0.0f, t.w11, v);
    return v;
}

// projective coords -> sample coords; constants folded:
// sx = (X/Z) * W/(W-1) - 0.5
#define CW (512.0f / 511.0f)
#define CH (512.0f / 511.0f)

__device__ __forceinline__ Taps proj_taps(float X, float Y, float Z) {
    float iz = __fdividef(1.0f, Z);
    float sx = fmaf(X * iz, CW, -0.5f);
    float sy = fmaf(Y * iz, CH, -0.5f);
    return make_taps(sx, sy);
}

// ---------------------------------------------------------------------------
// Fused kernel: block = one (batch,row); thread t handles x = t and x = t+256
// (strided so every warp's tap LDG spans only 32 consecutive columns = 128B)
// ---------------------------------------------------------------------------
__global__ void __launch_bounds__(THREADS)
pl_kernel(const float* __restrict__ Hp, const float* __restrict__ Ht,
          const float* __restrict__ I, float* __restrict__ out) {
    __shared__ float shp[9];
    __shared__ float sht[9];
    __shared__ float s_part[THREADS / 32];

    int tid = threadIdx.x;
    int b = blockIdx.x >> 9;
    int y = blockIdx.x & (HIMG - 1);

    if (tid == 0) invert3x3(Hp + b * 9, shp);
    if (tid == 1) invert3x3(Ht + b * 9, sht);
    __syncthreads();

    float fx = (float)tid, fy = (float)y;

    // projective coords for pixel A (x=tid); pixel B (x=tid+256) via increment
    float Xp = fmaf(shp[0], fx, fmaf(shp[1], fy, shp[2]));
    float Yp = fmaf(shp[3], fx, fmaf(shp[4], fy, shp[5]));
    float Zp = fmaf(shp[6], fx, fmaf(shp[7], fy, shp[8]));
    float Xt = fmaf(sht[0], fx, fmaf(sht[1], fy, sht[2]));
    float Yt = fmaf(sht[3], fx, fmaf(sht[4], fy, sht[5]));
    float Zt = fmaf(sht[6], fx, fmaf(sht[7], fy, sht[8]));

    Taps tpP0 = proj_taps(Xp, Yp, Zp);
    Taps tpT0 = proj_taps(Xt, Yt, Zt);
    Taps tpP1 = proj_taps(fmaf(shp[0], 256.0f, Xp),
                          fmaf(shp[3], 256.0f, Yp),
                          fmaf(shp[6], 256.0f, Zp));
    Taps tpT1 = proj_taps(fmaf(sht[0], 256.0f, Xt),
                          fmaf(sht[3], 256.0f, Yt),
                          fmaf(sht[6], 256.0f, Zt));

    const float* imgB = I + (size_t)b * (CHANNELS * PLANE);
    float acc = 0.0f;
#pragma unroll
    for (int c = 0; c < CHANNELS; c++) {
        const float* img = imgB + c * PLANE;
        float p0 = sample(img, tpP0);
        float t0 = sample(img, tpT0);
        float p1 = sample(img, tpP1);
        float t1 = sample(img, tpT1);
        float d0 = p0 - t0;
        float d1 = p1 - t1;
        acc = fmaf(d0, d0, acc);
        acc = fmaf(d1, d1, acc);
    }

    // warp shuffle -> smem -> one float atomic per block (pre-scaled)
#pragma unroll
    for (int off = 16; off > 0; off >>= 1)
        acc += __shfl_down_sync(0xFFFFFFFFu, acc, off);

    int lane = tid & 31, wid = tid >> 5;
    if (lane == 0) s_part[wid] = acc;
    __syncthreads();
    if (wid == 0) {
        float v = (lane < THREADS / 32) ? s_part[lane] : 0.0f;
#pragma unroll
        for (int off = 4; off > 0; off >>= 1)
            v += __shfl_down_sync(0xFFFFFFFFu, v, off);
        if (lane == 0) atomicAdd(out, v * INV_NELEM);
    }
}

extern "C" void kernel_launch(void* const* d_in, const int* in_sizes, int n_in,
                              void* d_out, int out_size) {
    const float* Hp = (const float*)d_in[0];
    const float* Ht = (const float*)d_in[1];
    const float* I  = (const float*)d_in[2];
    float* out = (float*)d_out;

    cudaMemsetAsync(out, 0, sizeof(float));
    pl_kernel<<<NBLOCKS, THREADS>>>(Hp, Ht, I, out);
}

// round 4
// speedup vs baseline: 1.2681x; 1.0105x over previous
#include <cuda_runtime.h>

#define BATCH     32
#define CHANNELS  3
#define HIMG      512
#define WIMG      512
#define PLANE     (HIMG * WIMG)
#define THREADS   256
#define NBLOCKS   (BATCH * HIMG)     // one block per (batch,row)
#define INV_NELEM (1.0f / (float)(BATCH * CHANNELS * HIMG * WIMG))

// self-resetting cross-block reduction state (zero-init at module load,
// restored to zero by the last block every launch -> graph-replay safe)
__device__ float        g_acc;
__device__ unsigned int g_ticket;

// ---------------------------------------------------------------------------
// 3x3 inverse via adjugate
// ---------------------------------------------------------------------------
__device__ __forceinline__ void invert3x3(const float* __restrict__ m,
                                          float* __restrict__ inv) {
    float c00 = m[4] * m[8] - m[5] * m[7];
    float c01 = m[5] * m[6] - m[3] * m[8];
    float c02 = m[3] * m[7] - m[4] * m[6];
    float det = m[0] * c00 + m[1] * c01 + m[2] * c02;
    float id  = 1.0f / det;
    inv[0] = c00 * id;
    inv[1] = (m[2] * m[7] - m[1] * m[8]) * id;
    inv[2] = (m[1] * m[5] - m[2] * m[4]) * id;
    inv[3] = c01 * id;
    inv[4] = (m[0] * m[8] - m[2] * m[6]) * id;
    inv[5] = (m[2] * m[3] - m[0] * m[5]) * id;
    inv[6] = c02 * id;
    inv[7] = (m[1] * m[6] - m[0] * m[7]) * id;
    inv[8] = (m[0] * m[4] - m[1] * m[3]) * id;
}

// ---------------------------------------------------------------------------
// Lean bilinear taps: NO clamps (offsets of invalid taps are never consumed
// because loads are predicated on w != 0), unsigned range tests, masked 1-D
// weights. NaN coords (Z~0 -> inf) are nulled by the selects.
// ---------------------------------------------------------------------------
struct Taps {
    int   o00;                  // o10=o00+1, o01=o00+512, o11=o00+513
    float w00, w10, w01, w11;
};

__device__ __forceinline__ Taps make_taps(float sx, float sy) {
    float x0f = floorf(sx), y0f = floorf(sy);
    float wx1 = sx - x0f, wx0 = 1.0f - wx1;
    float wy1 = sy - y0f, wy0 = 1.0f - wy1;
    int x0 = (int)x0f, y0 = (int)y0f;
    bool vx0 = (unsigned)x0       < WIMG;
    bool vx1 = (unsigned)(x0 + 1) < WIMG;
    bool vy0 = (unsigned)y0       < HIMG;
    bool vy1 = (unsigned)(y0 + 1) < HIMG;
    float wx0m = vx0 ? wx0 : 0.0f;
    float wx1m = vx1 ? wx1 : 0.0f;
    float wy0m = vy0 ? wy0 : 0.0f;
    float wy1m = vy1 ? wy1 : 0.0f;
    Taps tp;
    tp.o00 = y0 * WIMG + x0;
    tp.w00 = wx0m * wy0m;
    tp.w10 = wx1m * wy0m;
    tp.w01 = wx0m * wy1m;
    tp.w11 = wx1m * wy1m;
    return tp;
}

// predicated gather: zero-weight taps issue no memory access
__device__ __forceinline__ float sample(const float* __restrict__ img, const Taps& t) {
    float v = 0.0f;
    v = fmaf((t.w00 != 0.0f) ? __ldg(img + t.o00)            : 0.0f, t.w00, v);
    v = fmaf((t.w10 != 0.0f) ? __ldg(img + t.o00 + 1)        : 0.0f, t.w10, v);
    v = fmaf((t.w01 != 0.0f) ? __ldg(img + t.o00 + WIMG)     : 0.0f, t.w01, v);
    v = fmaf((t.w11 != 0.0f) ? __ldg(img + t.o00 + WIMG + 1) : 0.0f, t.w11, v);
    return v;
}

// sx = (X/Z) * W/(W-1) - 0.5   (folded reference chain, validated 1.4e-6)
#define CW (512.0f / 511.0f)
#define CH (512.0f / 511.0f)

__device__ __forceinline__ Taps proj_taps(float X, float Y, float Z) {
    float iz = __fdividef(1.0f, Z);
    float sx = fmaf(X * iz, CW, -0.5f);
    float sy = fmaf(Y * iz, CH, -0.5f);
    return make_taps(sx, sy);
}

// ---------------------------------------------------------------------------
// Fused kernel: block = one (batch,row); thread t handles x = t and x = t+256
// ---------------------------------------------------------------------------
__global__ void __launch_bounds__(THREADS)
pl_kernel(const float* __restrict__ Hp, const float* __restrict__ Ht,
          const float* __restrict__ I, float* __restrict__ out) {
    __shared__ float shp[9];
    __shared__ float sht[9];
    __shared__ float s_part[THREADS / 32];

    int tid = threadIdx.x;
    int b = blockIdx.x >> 9;
    int y = blockIdx.x & (HIMG - 1);

    if (tid == 0) invert3x3(Hp + b * 9, shp);
    if (tid == 1) invert3x3(Ht + b * 9, sht);
    __syncthreads();

    float fx = (float)tid, fy = (float)y;

    float Xp = fmaf(shp[0], fx, fmaf(shp[1], fy, shp[2]));
    float Yp = fmaf(shp[3], fx, fmaf(shp[4], fy, shp[5]));
    float Zp = fmaf(shp[6], fx, fmaf(shp[7], fy, shp[8]));
    float Xt = fmaf(sht[0], fx, fmaf(sht[1], fy, sht[2]));
    float Yt = fmaf(sht[3], fx, fmaf(sht[4], fy, sht[5]));
    float Zt = fmaf(sht[6], fx, fmaf(sht[7], fy, sht[8]));

    Taps tpP0 = proj_taps(Xp, Yp, Zp);
    Taps tpT0 = proj_taps(Xt, Yt, Zt);
    Taps tpP1 = proj_taps(fmaf(shp[0], 256.0f, Xp),
                          fmaf(shp[3], 256.0f, Yp),
                          fmaf(shp[6], 256.0f, Zp));
    Taps tpT1 = proj_taps(fmaf(sht[0], 256.0f, Xt),
                          fmaf(sht[3], 256.0f, Yt),
                          fmaf(sht[6], 256.0f, Zt));

    const float* imgB = I + (size_t)b * (CHANNELS * PLANE);
    float acc = 0.0f;
#pragma unroll
    for (int c = 0; c < CHANNELS; c++) {
        const float* img = imgB + c * PLANE;
        float p0 = sample(img, tpP0);
        float t0 = sample(img, tpT0);
        float p1 = sample(img, tpP1);
        float t1 = sample(img, tpT1);
        float d0 = p0 - t0;
        float d1 = p1 - t1;
        acc = fmaf(d0, d0, acc);
        acc = fmaf(d1, d1, acc);
    }

    // warp shuffle -> smem -> block partial
#pragma unroll
    for (int off = 16; off > 0; off >>= 1)
        acc += __shfl_down_sync(0xFFFFFFFFu, acc, off);

    int lane = tid & 31, wid = tid >> 5;
    if (lane == 0) s_part[wid] = acc;
    __syncthreads();
    if (tid == 0) {
        float v = 0.0f;
#pragma unroll
        for (int i = 0; i < THREADS / 32; i++) v += s_part[i];
        atomicAdd(&g_acc, v * INV_NELEM);
        __threadfence();
        unsigned t = atomicInc(&g_ticket, NBLOCKS - 1);  // wraps to 0 -> self-reset
        if (t == NBLOCKS - 1) {
            // last block: publish result and reset accumulator for next replay
            float r = atomicExch(&g_acc, 0.0f);
            out[0] = r;
        }
    }
}

extern "C" void kernel_launch(void* const* d_in, const int* in_sizes, int n_in,
                              void* d_out, int out_size) {
    const float* Hp = (const float*)d_in[0];
    const float* Ht = (const float*)d_in[1];
    const float* I  = (const float*)d_in[2];
    float* out = (float*)d_out;

    pl_kernel<<<NBLOCKS, THREADS>>>(Hp, Ht, I, out);
}